// round 14
// baseline (speedup 1.0000x reference)
#include <cuda_runtime.h>

#define B_ 4
#define T_ 128
#define S_ 512
#define D_ 512

// Scratch (allocation-free rule: __device__ globals)
__device__ __align__(16) float g_wq [B_ * T_ * D_];          // 1 MB
__device__ __align__(16) float g_uh [B_ * S_ * D_];          // 4 MB
__device__ __align__(16) float g_pre[B_ * T_ * D_];          // 1 MB  inp @ WoutR^T + bout
__device__ __align__(16) float g_c  [B_ * T_ * D_];          // 1 MB  context vectors

__device__ __forceinline__ float fast_tanh(float x) {
    float y;
    asm("tanh.approx.f32 %0, %1;" : "=f"(y) : "f"(x));
    return y;
}

__device__ __forceinline__ unsigned to_tf32(float x) {
    unsigned u;
    asm("cvt.rna.tf32.f32 %0, %1;" : "=r"(u) : "f"(x));
    return u;
}

__device__ __forceinline__ void mma_tf32(float* d, const unsigned* a, const unsigned* b) {
    asm volatile(
        "mma.sync.aligned.m16n8k8.row.col.f32.tf32.tf32.f32 "
        "{%0,%1,%2,%3}, {%4,%5,%6,%7}, {%8,%9}, {%0,%1,%2,%3};"
        : "+f"(d[0]), "+f"(d[1]), "+f"(d[2]), "+f"(d[3])
        : "r"(a[0]), "r"(a[1]), "r"(a[2]), "r"(a[3]), "r"(b[0]), "r"(b[1]));
}

__device__ __forceinline__ void ldsm_x4(unsigned& r0, unsigned& r1,
                                        unsigned& r2, unsigned& r3,
                                        unsigned addr) {
    asm volatile(
        "ldmatrix.sync.aligned.m8n8.x4.shared.b16 {%0,%1,%2,%3}, [%4];"
        : "=r"(r0), "=r"(r1), "=r"(r2), "=r"(r3) : "r"(addr));
}

// Value-folding butterfly merge: lanes with (lane&mask)==0 end up owning the
// lo-indexed value's pair-sum; lanes with bit set own the hi-indexed one.
__device__ __forceinline__ float merge2(float lo, float hi, int mask, int lane) {
    const bool up = (lane & mask) != 0;
    float mine  = up ? hi : lo;
    float other = up ? lo : hi;
    return mine + __shfl_xor_sync(0xFFFFFFFFu, other, mask);
}

// ---------------------------------------------------------------------------
// Segmented NT GEMM on tensor cores (tf32 HMMA, fp32 accumulate).
//   C[m,n] = sum_k A[m,k]*W[n,k] (+bias[n]) (+addC[m,n])
// BM=128, BN=64, BK=16, 256 threads = 8 warps (4m x 2n); warp tile m32 x n32
// -> per k8-step: 4 ldmatrix.x4 feed 8 MMAs (halved smem bytes per MAC).
// A and W staged [row][k], pad 16->20 words (ldmatrix reads conflict-free).
// ---------------------------------------------------------------------------
struct GemmArgs {
    const float* A[3];
    const float* W[3];
    const float* bias[3];
    const float* addC[3];     // optional per-(m,n) addend (uses ldc)
    float*       C[3];
    int lda[3], ldw[3], ldc[3];
    int segEnd[3];            // cumulative m-block boundaries (BM=128)
};

__global__ __launch_bounds__(256) void gemm_seg_kernel(GemmArgs args, int K)
{
    __shared__ unsigned As[2][128][20];  // [m][k] tf32 bits
    __shared__ unsigned Ws[2][64][20];   // [n][k] tf32 bits

    const int bm = blockIdx.x;
    int seg = 0;
    if (bm >= args.segEnd[0]) seg = 1;
    if (bm >= args.segEnd[1]) seg = 2;
    const int segStart = (seg == 0) ? 0 : args.segEnd[seg - 1];

    const float* A    = args.A[seg];
    const float* W    = args.W[seg];
    const float* bias = args.bias[seg];
    const float* addC = args.addC[seg];
    float*       C    = args.C[seg];
    const int lda = args.lda[seg], ldw = args.ldw[seg], ldc = args.ldc[seg];

    const int m0 = (bm - segStart) * 128;
    const int n0 = blockIdx.y * 64;

    const int tid  = threadIdx.x;
    const int warp = tid >> 5;
    const int lane = tid & 31;
    const int wm   = warp >> 1;          // 0..3  (m32 tile)
    const int wn   = warp & 1;           // 0..1  (n32 tile)
    const int grp  = lane >> 3 == 0 ? lane >> 2 : lane >> 2; // placeholder opt-out
    const int g8   = lane >> 2;          // 0..7 (mma row group)
    const int qid  = lane & 3;           // 0..3

    const int lr = tid >> 2;             // 0..63 staging row
    const int lc = (tid & 3) * 4;        // 0,4,8,12 staging k

    // ldmatrix per-lane base addresses
    const int q  = lane >> 3;            // quadrant 0..3
    const int qr = lane & 7;             // row within quadrant
    unsigned baseAs, baseWs;
    {
        unsigned a32 = (unsigned)__cvta_generic_to_shared(&As[0][0][0]);
        unsigned w32 = (unsigned)__cvta_generic_to_shared(&Ws[0][0][0]);
        // A quadrants: rows {+0,+8,+0,+8}, cols {0,0,4,4}
        const int arow = wm * 32 + (q & 1) * 8 + qr;
        const int acol = (q >> 1) * 4;
        baseAs = a32 + (unsigned)((arow * 20 + acol) * 4);
        // B quadrants: rows {+0,+0,+8,+8}, cols {0,4,0,4}
        const int brow = wn * 32 + (q >> 1) * 8 + qr;
        const int bcol = (q & 1) * 4;
        baseWs = w32 + (unsigned)((brow * 20 + bcol) * 4);
    }
    const unsigned ABUF = 128u * 20u * 4u;  // 10240 bytes per A buffer
    const unsigned WBUF = 64u * 20u * 4u;   // 5120 bytes per W buffer
    const unsigned ROW16 = 16u * 20u * 4u;  // 16 rows

    const float* Aptr0 = A + (long)(m0 + lr) * lda + lc;
    const float* Aptr1 = A + (long)(m0 + lr + 64) * lda + lc;
    const float* Wptr  = W + (long)(n0 + lr) * ldw + lc;
    const int nChunks = K / 16;

    float acc[2][4][4] = {};             // [mi][nj][4]

    // stage chunk 0
    float4 pa0 = *(const float4*)Aptr0;
    float4 pa1 = *(const float4*)Aptr1;
    float4 pw  = *(const float4*)Wptr;
    {
        uint4 u0 = make_uint4(to_tf32(pa0.x), to_tf32(pa0.y), to_tf32(pa0.z), to_tf32(pa0.w));
        uint4 u1 = make_uint4(to_tf32(pa1.x), to_tf32(pa1.y), to_tf32(pa1.z), to_tf32(pa1.w));
        uint4 uw = make_uint4(to_tf32(pw.x),  to_tf32(pw.y),  to_tf32(pw.z),  to_tf32(pw.w));
        *(uint4*)&As[0][lr][lc]      = u0;
        *(uint4*)&As[0][lr + 64][lc] = u1;
        *(uint4*)&Ws[0][lr][lc]      = uw;
    }

    for (int c = 0; c < nChunks; c++) {
        __syncthreads();
        const int buf = c & 1;
        const unsigned aoff = buf ? ABUF : 0u;
        const unsigned woff = buf ? WBUF : 0u;
        if (c + 1 < nChunks) {
            pa0 = *(const float4*)(Aptr0 + (c + 1) * 16);
            pa1 = *(const float4*)(Aptr1 + (c + 1) * 16);
            pw  = *(const float4*)(Wptr  + (c + 1) * 16);
        }

        #pragma unroll
        for (int s = 0; s < 2; s++) {    // two k8 steps per chunk
            const unsigned soff = (unsigned)(s * 32);
            unsigned afr[2][4], bfr[2][4];
            ldsm_x4(afr[0][0], afr[0][1], afr[0][2], afr[0][3], baseAs + aoff + soff);
            ldsm_x4(afr[1][0], afr[1][1], afr[1][2], afr[1][3], baseAs + aoff + soff + ROW16);
            ldsm_x4(bfr[0][0], bfr[0][1], bfr[0][2], bfr[0][3], baseWs + woff + soff);
            ldsm_x4(bfr[1][0], bfr[1][1], bfr[1][2], bfr[1][3], baseWs + woff + soff + ROW16);
            #pragma unroll
            for (int i = 0; i < 2; i++) {
                mma_tf32(acc[i][0], afr[i], &bfr[0][0]);
                mma_tf32(acc[i][1], afr[i], &bfr[0][2]);
                mma_tf32(acc[i][2], afr[i], &bfr[1][0]);
                mma_tf32(acc[i][3], afr[i], &bfr[1][2]);
            }
        }

        if (c + 1 < nChunks) {
            const int nb = buf ^ 1;
            uint4 u0 = make_uint4(to_tf32(pa0.x), to_tf32(pa0.y), to_tf32(pa0.z), to_tf32(pa0.w));
            uint4 u1 = make_uint4(to_tf32(pa1.x), to_tf32(pa1.y), to_tf32(pa1.z), to_tf32(pa1.w));
            uint4 uw = make_uint4(to_tf32(pw.x),  to_tf32(pw.y),  to_tf32(pw.z),  to_tf32(pw.w));
            *(uint4*)&As[nb][lr][lc]      = u0;
            *(uint4*)&As[nb][lr + 64][lc] = u1;
            *(uint4*)&Ws[nb][lr][lc]      = uw;
        }
    }

    // Epilogue: per m16n8 tile, rows {g8, g8+8}, cols {2qid, 2qid+1}
    #pragma unroll
    for (int j = 0; j < 4; j++) {
        const int n = n0 + wn * 32 + j * 8 + 2 * qid;
        float b0 = 0.f, b1 = 0.f;
        if (bias) { b0 = bias[n]; b1 = bias[n + 1]; }
        #pragma unroll
        for (int i = 0; i < 2; i++) {
            const int m = m0 + wm * 32 + i * 16 + g8;
            float2 r0 = make_float2(acc[i][j][0] + b0, acc[i][j][1] + b1);
            float2 r1 = make_float2(acc[i][j][2] + b0, acc[i][j][3] + b1);
            if (addC) {
                float2 p0 = *(const float2*)(addC + (long)m * ldc + n);
                float2 p1 = *(const float2*)(addC + (long)(m + 8) * ldc + n);
                r0.x += p0.x; r0.y += p0.y;
                r1.x += p1.x; r1.y += p1.y;
            }
            *(float2*)(C + (long)m * ldc + n)       = r0;
            *(float2*)(C + (long)(m + 8) * ldc + n) = r1;
        }
    }
}

// ---------------------------------------------------------------------------
// Fused score + tanh + softmax + context-vector. TILE_T=4.
// Grid: (T/4, B), 512 threads (16 warps). Warp handles s-pairs with
// register double-buffered uh rows (LDG latency hidden under MUFU work)
// and a 9-shuffle packed reduction.
// ---------------------------------------------------------------------------
__global__ __launch_bounds__(512) void attn_kernel(
        const float* __restrict__ wq,
        const float* __restrict__ uh,
        const float* __restrict__ v,
        const float* __restrict__ context,
        float* __restrict__ align_out,
        float* __restrict__ c_out)
{
    __shared__ float v_sh[D_];
    __shared__ float wq_sh[4][D_];
    __shared__ float al_sh[4][S_];

    const int b = blockIdx.y;
    const int t0 = blockIdx.x * 4;
    const int tid = threadIdx.x;
    const int warp = tid >> 5;
    const int lane = tid & 31;

    {
        v_sh[tid] = v[tid];
        #pragma unroll
        for (int tt = 0; tt < 4; tt++)
            wq_sh[tt][tid] = wq[((long)(b * T_ + t0 + tt)) * D_ + tid];
    }
    __syncthreads();

    // ---- scores: warp handles s-pairs {2w, 2w+1} stepping by 32 ----
    const int s0 = warp * 2;
    float4 cu0[4], cu1[4];
    {
        const float4* u0 = (const float4*)(uh + ((long)(b * S_ + s0)) * D_);
        const float4* u1 = u0 + (D_ / 4);
        #pragma unroll
        for (int i = 0; i < 4; i++) {
            cu0[i] = u0[lane + 32 * i];
            cu1[i] = u1[lane + 32 * i];
        }
    }

    for (int s = s0; s < S_; s += 32) {
        const int sn = s + 32;
        float4 nu0[4], nu1[4];
        if (sn < S_) {
            const float4* u0 = (const float4*)(uh + ((long)(b * S_ + sn)) * D_);
            const float4* u1 = u0 + (D_ / 4);
            #pragma unroll
            for (int i = 0; i < 4; i++) {
                nu0[i] = u0[lane + 32 * i];
                nu1[i] = u1[lane + 32 * i];
            }
        }

        float acc[2][4] = {};
        #pragma unroll
        for (int i = 0; i < 4; i++) {
            const int idx = lane + 32 * i;
            float4 vf = ((const float4*)v_sh)[idx];
            float4 q0 = ((const float4*)wq_sh[0])[idx];
            float4 q1 = ((const float4*)wq_sh[1])[idx];
            float4 q2 = ((const float4*)wq_sh[2])[idx];
            float4 q3 = ((const float4*)wq_sh[3])[idx];
            float u0a[4] = {cu0[i].x, cu0[i].y, cu0[i].z, cu0[i].w};
            float u1a[4] = {cu1[i].x, cu1[i].y, cu1[i].z, cu1[i].w};
            float va[4]  = {vf.x, vf.y, vf.z, vf.w};
            float qa[4][4] = {{q0.x, q0.y, q0.z, q0.w},
                              {q1.x, q1.y, q1.z, q1.w},
                              {q2.x, q2.y, q2.z, q2.w},
                              {q3.x, q3.y, q3.z, q3.w}};
            #pragma unroll
            for (int cidx = 0; cidx < 4; cidx++) {
                const float vd = va[cidx];
                #pragma unroll
                for (int tt = 0; tt < 4; tt++) {
                    acc[0][tt] = fmaf(vd, fast_tanh(u0a[cidx] + qa[tt][cidx]), acc[0][tt]);
                    acc[1][tt] = fmaf(vd, fast_tanh(u1a[cidx] + qa[tt][cidx]), acc[1][tt]);
                }
            }
        }

        // ---- packed reduction: 8 values -> 9 shuffles ----
        // v8[4p+tt]; after folding, lane l<8 holds full sum of v8[l].
        float w0 = merge2(acc[0][0], acc[0][1], 1, lane);
        float w1 = merge2(acc[0][2], acc[0][3], 1, lane);
        float w2 = merge2(acc[1][0], acc[1][1], 1, lane);
        float w3 = merge2(acc[1][2], acc[1][3], 1, lane);
        float x0 = merge2(w0, w1, 2, lane);
        float x1 = merge2(w2, w3, 2, lane);
        float y  = merge2(x0, x1, 4, lane);
        y += __shfl_xor_sync(0xFFFFFFFFu, y, 8);
        y += __shfl_xor_sync(0xFFFFFFFFu, y, 16);
        if (lane < 8)
            al_sh[lane & 3][s + (lane >> 2)] = y;

        #pragma unroll
        for (int i = 0; i < 4; i++) { cu0[i] = nu0[i]; cu1[i] = nu1[i]; }
    }
    __syncthreads();

    // ---- softmax over s: warp tt handles row t0+tt ----
    if (warp < 4) {
        float m = -1e30f;
        for (int s = lane; s < S_; s += 32) m = fmaxf(m, al_sh[warp][s]);
        #pragma unroll
        for (int o = 16; o; o >>= 1)
            m = fmaxf(m, __shfl_xor_sync(0xFFFFFFFFu, m, o));
        float sum = 0.f;
        for (int s = lane; s < S_; s += 32) {
            float e = __expf(al_sh[warp][s] - m);
            al_sh[warp][s] = e;
            sum += e;
        }
        #pragma unroll
        for (int o = 16; o; o >>= 1)
            sum += __shfl_xor_sync(0xFFFFFFFFu, sum, o);
        float inv = 1.0f / sum;
        float* aout = align_out + ((long)(b * T_ + t0 + warp)) * S_;
        for (int s = lane; s < S_; s += 32) {
            float p = al_sh[warp][s] * inv;
            al_sh[warp][s] = p;
            aout[s] = p;
        }
    }
    __syncthreads();

    // ---- context vectors: c[tt][d] = sum_s p[tt][s]*context[b,s,d]; d=tid ----
    const int d = tid;
    float c0 = 0.f, c1 = 0.f, c2 = 0.f, c3 = 0.f;
    const float* cptr = context + ((long)b * S_) * D_ + d;
    #pragma unroll 4
    for (int s = 0; s < S_; s++) {
        float cx = cptr[(long)s * D_];
        c0 = fmaf(al_sh[0][s], cx, c0);
        c1 = fmaf(al_sh[1][s], cx, c1);
        c2 = fmaf(al_sh[2][s], cx, c2);
        c3 = fmaf(al_sh[3][s], cx, c3);
    }
    c_out[((long)(b * T_ + t0 + 0)) * D_ + d] = c0;
    c_out[((long)(b * T_ + t0 + 1)) * D_ + d] = c1;
    c_out[((long)(b * T_ + t0 + 2)) * D_ + d] = c2;
    c_out[((long)(b * T_ + t0 + 3)) * D_ + d] = c3;
}

// ---------------------------------------------------------------------------
extern "C" void kernel_launch(void* const* d_in, const int* in_sizes, int n_in,
                              void* d_out, int out_size)
{
    const float* inp     = (const float*)d_in[0];
    const float* context = (const float*)d_in[1];
    const float* Wq      = (const float*)d_in[2];
    const float* bq      = (const float*)d_in[3];
    const float* Wc      = (const float*)d_in[4];
    const float* v       = (const float*)d_in[5];
    const float* Wout    = (const float*)d_in[6];
    const float* bout    = (const float*)d_in[7];

    float* out    = (float*)d_out;
    float* attn_h = out;                         // (B,T,D)
    float* align  = out + (long)B_ * T_ * D_;    // (B,T,S)

    float *p_wq, *p_uh, *p_pre, *p_c;
    cudaGetSymbolAddress((void**)&p_wq, g_wq);
    cudaGetSymbolAddress((void**)&p_uh, g_uh);
    cudaGetSymbolAddress((void**)&p_pre, g_pre);
    cudaGetSymbolAddress((void**)&p_c, g_c);

    // ---- Launch 1: fused {wq, uh, pre} GEMMs, all K=512, BM=128 ----
    GemmArgs a1;
    // seg0: wq = inp @ Wq^T + bq             (M=512 -> 4 blocks)
    a1.A[0] = inp;     a1.W[0] = Wq;          a1.bias[0] = bq;      a1.addC[0] = nullptr;
    a1.C[0] = p_wq;    a1.lda[0] = D_;        a1.ldw[0] = D_;       a1.ldc[0] = D_;
    // seg1: uh = context @ Wc^T              (M=2048 -> 16 blocks)
    a1.A[1] = context; a1.W[1] = Wc;          a1.bias[1] = nullptr; a1.addC[1] = nullptr;
    a1.C[1] = p_uh;    a1.lda[1] = D_;        a1.ldw[1] = D_;       a1.ldc[1] = D_;
    // seg2: pre = inp @ WoutR^T + bout       (M=512 -> 4 blocks)
    a1.A[2] = inp;     a1.W[2] = Wout + D_;   a1.bias[2] = bout;    a1.addC[2] = nullptr;
    a1.C[2] = p_pre;   a1.lda[2] = D_;        a1.ldw[2] = 2 * D_;   a1.ldc[2] = D_;
    a1.segEnd[0] = 4; a1.segEnd[1] = 20; a1.segEnd[2] = 24;
    gemm_seg_kernel<<<dim3(24, 8, 1), 256>>>(a1, D_);

    // ---- Launch 2: fused scores + softmax + context vectors ----
    attn_kernel<<<dim3(T_ / 4, B_), 512>>>(p_wq, p_uh, v, context, align, p_c);

    // ---- Launch 3: attn_h = c @ WoutL^T + pre  (full K, epilogue fold) ----
    GemmArgs a3;
    a3.A[0] = p_c;  a3.W[0] = Wout;  a3.bias[0] = nullptr;  a3.addC[0] = p_pre;
    a3.C[0] = attn_h;
    a3.lda[0] = D_; a3.ldw[0] = 2 * D_; a3.ldc[0] = D_;
    a3.A[1] = a3.A[0]; a3.W[1] = a3.W[0]; a3.bias[1] = nullptr; a3.addC[1] = nullptr;
    a3.C[1] = a3.C[0]; a3.lda[1] = a3.lda[0]; a3.ldw[1] = a3.ldw[0]; a3.ldc[1] = a3.ldc[0];
    a3.A[2] = a3.A[0]; a3.W[2] = a3.W[0]; a3.bias[2] = nullptr; a3.addC[2] = nullptr;
    a3.C[2] = a3.C[0]; a3.lda[2] = a3.lda[0]; a3.ldw[2] = a3.ldw[0]; a3.ldc[2] = a3.ldc[0];
    a3.segEnd[0] = 4; a3.segEnd[1] = 4; a3.segEnd[2] = 4;
    gemm_seg_kernel<<<dim3(4, 8, 1), 256>>>(a3, D_);
}

// round 15
// speedup vs baseline: 1.3643x; 1.3643x over previous
#include <cuda_runtime.h>

#define B_ 4
#define T_ 128
#define S_ 512
#define D_ 512

// Scratch (allocation-free rule: __device__ globals)
__device__ __align__(16) float g_wq [B_ * T_ * D_];          // 1 MB
__device__ __align__(16) float g_uh [B_ * S_ * D_];          // 4 MB
__device__ __align__(16) float g_pre[B_ * T_ * D_];          // 1 MB  inp @ WoutR^T + bout
__device__ __align__(16) float g_c  [B_ * T_ * D_];          // 1 MB  context vectors

__device__ __forceinline__ float fast_tanh(float x) {
    float y;
    asm("tanh.approx.f32 %0, %1;" : "=f"(y) : "f"(x));
    return y;
}

__device__ __forceinline__ unsigned to_tf32(float x) {
    unsigned u;
    asm("cvt.rna.tf32.f32 %0, %1;" : "=r"(u) : "f"(x));
    return u;
}

__device__ __forceinline__ unsigned cvt_bits_tf32(unsigned x) {
    unsigned u;
    asm("cvt.rna.tf32.f32 %0, %1;" : "=r"(u) : "f"(__uint_as_float(x)));
    return u;
}

__device__ __forceinline__ void mma_tf32(float* d, const unsigned* a, const unsigned* b) {
    asm volatile(
        "mma.sync.aligned.m16n8k8.row.col.f32.tf32.tf32.f32 "
        "{%0,%1,%2,%3}, {%4,%5,%6,%7}, {%8,%9}, {%0,%1,%2,%3};"
        : "+f"(d[0]), "+f"(d[1]), "+f"(d[2]), "+f"(d[3])
        : "r"(a[0]), "r"(a[1]), "r"(a[2]), "r"(a[3]), "r"(b[0]), "r"(b[1]));
}

__device__ __forceinline__ void ldsm_x4(unsigned& r0, unsigned& r1,
                                        unsigned& r2, unsigned& r3,
                                        unsigned addr) {
    asm volatile(
        "ldmatrix.sync.aligned.m8n8.x4.shared.b16 {%0,%1,%2,%3}, [%4];"
        : "=r"(r0), "=r"(r1), "=r"(r2), "=r"(r3) : "r"(addr));
}

__device__ __forceinline__ void cp_async16(unsigned saddr, const void* gptr) {
    asm volatile("cp.async.cg.shared.global [%0], [%1], 16;"
                 :: "r"(saddr), "l"(gptr));
}
__device__ __forceinline__ void cp_commit() {
    asm volatile("cp.async.commit_group;");
}
__device__ __forceinline__ void cp_wait2() {
    asm volatile("cp.async.wait_group 2;");
}

// ---------------------------------------------------------------------------
// Segmented NT GEMM on tensor cores (tf32 HMMA, fp32 accumulate).
//   C[m,n] = sum_k A[m,k]*W[n,k] (+bias[n]) (+addC[m,n])
// R13 tiling: BM=BN=64, BK=16, 256 threads = 8 warps (2m x 4n), warp tile
// m32 x n16. NEW: 4-stage cp.async pipeline (3 chunks in flight), raw f32
// staged in smem, tf32 cvt applied to fragments after ldmatrix.
// ---------------------------------------------------------------------------
struct GemmArgs {
    const float* A[3];
    const float* W[3];
    const float* bias[3];
    const float* addC[3];     // optional per-(m,n) addend (uses ldc)
    float*       C[3];
    int lda[3], ldw[3], ldc[3];
    int segEnd[3];            // cumulative m-block boundaries (BM=64)
};

#define STAGES 4
#define STAGE_BYTES (64u * 20u * 4u)   // 5120 bytes per tile-stage

__global__ __launch_bounds__(256) void gemm_seg_kernel(GemmArgs args, int K)
{
    __shared__ unsigned As[STAGES][64][20];  // [m][k] raw f32 bits
    __shared__ unsigned Ws[STAGES][64][20];  // [n][k] raw f32 bits

    const int bm = blockIdx.x;
    int seg = 0;
    if (bm >= args.segEnd[0]) seg = 1;
    if (bm >= args.segEnd[1]) seg = 2;
    const int segStart = (seg == 0) ? 0 : args.segEnd[seg - 1];

    const float* A    = args.A[seg];
    const float* W    = args.W[seg];
    const float* bias = args.bias[seg];
    const float* addC = args.addC[seg];
    float*       C    = args.C[seg];
    const int lda = args.lda[seg], ldw = args.ldw[seg], ldc = args.ldc[seg];

    const int m0 = (bm - segStart) * 64;
    const int n0 = blockIdx.y * 64;

    const int tid  = threadIdx.x;
    const int warp = tid >> 5;
    const int lane = tid & 31;
    const int wm   = warp >> 2;          // 0..1  (m32 tile)
    const int wn   = warp & 3;           // 0..3  (n16 tile)
    const int grp  = lane >> 2;          // 0..7
    const int qid  = lane & 3;           // 0..3

    const int lr = tid >> 2;             // 0..63 staging row
    const int lc = (tid & 3) * 4;        // 0,4,8,12 staging k

    // ldmatrix per-lane base addresses (stage 0)
    const int q  = lane >> 3;            // quadrant 0..3
    const int qr = lane & 7;             // row within quadrant
    unsigned baseAs, baseWs;
    {
        unsigned a32 = (unsigned)__cvta_generic_to_shared(&As[0][0][0]);
        unsigned w32 = (unsigned)__cvta_generic_to_shared(&Ws[0][0][0]);
        // A quadrants: rows {+0,+8,+0,+8}, cols {0,0,4,4}
        const int arow = wm * 32 + (q & 1) * 8 + qr;
        const int acol = (q >> 1) * 4;
        baseAs = a32 + (unsigned)((arow * 20 + acol) * 4);
        // B quadrants: rows {+0,+0,+8,+8}, cols {0,4,0,4}
        const int brow = wn * 16 + (q >> 1) * 8 + qr;
        const int bcol = (q & 1) * 4;
        baseWs = w32 + (unsigned)((brow * 20 + bcol) * 4);
    }

    // cp.async staging addresses (stage 0)
    unsigned stA = (unsigned)__cvta_generic_to_shared(&As[0][lr][lc]);
    unsigned stW = (unsigned)__cvta_generic_to_shared(&Ws[0][lr][lc]);
    const float* Ag = A + (long)(m0 + lr) * lda + lc;
    const float* Wg = W + (long)(n0 + lr) * ldw + lc;
    const int nChunks = K / 16;

    float acc[2][2][4] = {};             // [mi][nj][4]

    // prologue: issue STAGES-1 chunks
    #pragma unroll
    for (int p = 0; p < STAGES - 1; p++) {
        if (p < nChunks) {
            cp_async16(stA + p * STAGE_BYTES, Ag + p * 16);
            cp_async16(stW + p * STAGE_BYTES, Wg + p * 16);
        }
        cp_commit();
    }

    for (int c = 0; c < nChunks; c++) {
        cp_wait2();                      // chunk c landed
        __syncthreads();

        const int pf = c + STAGES - 1;   // prefetch chunk
        if (pf < nChunks) {
            const unsigned so = (unsigned)(pf & (STAGES - 1)) * STAGE_BYTES;
            cp_async16(stA + so, Ag + pf * 16);
            cp_async16(stW + so, Wg + pf * 16);
        }
        cp_commit();

        const unsigned boff = (unsigned)(c & (STAGES - 1)) * STAGE_BYTES;
        #pragma unroll
        for (int s = 0; s < 2; s++) {    // two k8 steps per chunk
            const unsigned soff = boff + (unsigned)(s * 32);
            unsigned afr[2][4], bfr[4];
            ldsm_x4(afr[0][0], afr[0][1], afr[0][2], afr[0][3], baseAs + soff);
            ldsm_x4(afr[1][0], afr[1][1], afr[1][2], afr[1][3],
                    baseAs + soff + 16u * 20u * 4u);
            ldsm_x4(bfr[0], bfr[1], bfr[2], bfr[3], baseWs + soff);
            #pragma unroll
            for (int r = 0; r < 4; r++) {
                afr[0][r] = cvt_bits_tf32(afr[0][r]);
                afr[1][r] = cvt_bits_tf32(afr[1][r]);
                bfr[r]    = cvt_bits_tf32(bfr[r]);
            }
            #pragma unroll
            for (int i = 0; i < 2; i++) {
                mma_tf32(acc[i][0], afr[i], &bfr[0]);
                mma_tf32(acc[i][1], afr[i], &bfr[2]);
            }
        }
    }

    // Epilogue: D fragment rows {grp, grp+8}, cols {2qid, 2qid+1}
    #pragma unroll
    for (int j = 0; j < 2; j++) {
        const int n = n0 + wn * 16 + j * 8 + 2 * qid;
        float b0 = 0.f, b1 = 0.f;
        if (bias) { b0 = bias[n]; b1 = bias[n + 1]; }
        #pragma unroll
        for (int i = 0; i < 2; i++) {
            const int m = m0 + wm * 32 + i * 16 + grp;
            float2 r0 = make_float2(acc[i][j][0] + b0, acc[i][j][1] + b1);
            float2 r1 = make_float2(acc[i][j][2] + b0, acc[i][j][3] + b1);
            if (addC) {
                float2 p0 = *(const float2*)(addC + (long)m * ldc + n);
                float2 p1 = *(const float2*)(addC + (long)(m + 8) * ldc + n);
                r0.x += p0.x; r0.y += p0.y;
                r1.x += p1.x; r1.y += p1.y;
            }
            *(float2*)(C + (long)m * ldc + n)       = r0;
            *(float2*)(C + (long)(m + 8) * ldc + n) = r1;
        }
    }
}

// ---------------------------------------------------------------------------
// Fused score + tanh + softmax + context-vector. TILE_T=4.  (R13 version)
// Grid: (T/4, B), 512 threads (16 warps). Each warp handles s-PAIRS
// (s, s+1), vectorized float4 loads, 8 independent accumulator chains.
// ---------------------------------------------------------------------------
__global__ __launch_bounds__(512) void attn_kernel(
        const float* __restrict__ wq,
        const float* __restrict__ uh,
        const float* __restrict__ v,
        const float* __restrict__ context,
        float* __restrict__ align_out,
        float* __restrict__ c_out)
{
    __shared__ float v_sh[D_];
    __shared__ float wq_sh[4][D_];
    __shared__ float al_sh[4][S_];

    const int b = blockIdx.y;
    const int t0 = blockIdx.x * 4;
    const int tid = threadIdx.x;
    const int warp = tid >> 5;
    const int lane = tid & 31;

    {
        v_sh[tid] = v[tid];
        #pragma unroll
        for (int tt = 0; tt < 4; tt++)
            wq_sh[tt][tid] = wq[((long)(b * T_ + t0 + tt)) * D_ + tid];
    }
    __syncthreads();

    // ---- scores: warp handles s-pairs {2w, 2w+1} stepping by 32 ----
    for (int s = warp * 2; s < S_; s += 32) {
        const float4* u0 = (const float4*)(uh + ((long)(b * S_ + s)) * D_);
        const float4* u1 = u0 + (D_ / 4);
        float acc[2][4] = {};
        #pragma unroll
        for (int i = 0; i < 4; i++) {
            const int idx = lane + 32 * i;
            float4 x0 = u0[idx];
            float4 x1 = u1[idx];
            float4 vf = ((const float4*)v_sh)[idx];
            float4 q0 = ((const float4*)wq_sh[0])[idx];
            float4 q1 = ((const float4*)wq_sh[1])[idx];
            float4 q2 = ((const float4*)wq_sh[2])[idx];
            float4 q3 = ((const float4*)wq_sh[3])[idx];
            float u0a[4] = {x0.x, x0.y, x0.z, x0.w};
            float u1a[4] = {x1.x, x1.y, x1.z, x1.w};
            float va[4]  = {vf.x, vf.y, vf.z, vf.w};
            float qa[4][4] = {{q0.x, q0.y, q0.z, q0.w},
                              {q1.x, q1.y, q1.z, q1.w},
                              {q2.x, q2.y, q2.z, q2.w},
                              {q3.x, q3.y, q3.z, q3.w}};
            #pragma unroll
            for (int cidx = 0; cidx < 4; cidx++) {
                const float vd = va[cidx];
                #pragma unroll
                for (int tt = 0; tt < 4; tt++) {
                    acc[0][tt] = fmaf(vd, fast_tanh(u0a[cidx] + qa[tt][cidx]), acc[0][tt]);
                    acc[1][tt] = fmaf(vd, fast_tanh(u1a[cidx] + qa[tt][cidx]), acc[1][tt]);
                }
            }
        }
        #pragma unroll
        for (int o = 16; o; o >>= 1) {
            #pragma unroll
            for (int p = 0; p < 2; p++)
                #pragma unroll
                for (int tt = 0; tt < 4; tt++)
                    acc[p][tt] += __shfl_xor_sync(0xFFFFFFFFu, acc[p][tt], o);
        }
        if (lane == 0) {
            #pragma unroll
            for (int tt = 0; tt < 4; tt++) {
                al_sh[tt][s]     = acc[0][tt];
                al_sh[tt][s + 1] = acc[1][tt];
            }
        }
    }
    __syncthreads();

    // ---- softmax over s: warp tt handles row t0+tt ----
    if (warp < 4) {
        float m = -1e30f;
        for (int s = lane; s < S_; s += 32) m = fmaxf(m, al_sh[warp][s]);
        #pragma unroll
        for (int o = 16; o; o >>= 1)
            m = fmaxf(m, __shfl_xor_sync(0xFFFFFFFFu, m, o));
        float sum = 0.f;
        for (int s = lane; s < S_; s += 32) {
            float e = __expf(al_sh[warp][s] - m);
            al_sh[warp][s] = e;
            sum += e;
        }
        #pragma unroll
        for (int o = 16; o; o >>= 1)
            sum += __shfl_xor_sync(0xFFFFFFFFu, sum, o);
        float inv = 1.0f / sum;
        float* aout = align_out + ((long)(b * T_ + t0 + warp)) * S_;
        for (int s = lane; s < S_; s += 32) {
            float p = al_sh[warp][s] * inv;
            al_sh[warp][s] = p;
            aout[s] = p;
        }
    }
    __syncthreads();

    // ---- context vectors: c[tt][d] = sum_s p[tt][s]*context[b,s,d]; d=tid ----
    const int d = tid;
    float c0 = 0.f, c1 = 0.f, c2 = 0.f, c3 = 0.f;
    const float* cptr = context + ((long)b * S_) * D_ + d;
    #pragma unroll 4
    for (int s = 0; s < S_; s++) {
        float cx = cptr[(long)s * D_];
        c0 = fmaf(al_sh[0][s], cx, c0);
        c1 = fmaf(al_sh[1][s], cx, c1);
        c2 = fmaf(al_sh[2][s], cx, c2);
        c3 = fmaf(al_sh[3][s], cx, c3);
    }
    c_out[((long)(b * T_ + t0 + 0)) * D_ + d] = c0;
    c_out[((long)(b * T_ + t0 + 1)) * D_ + d] = c1;
    c_out[((long)(b * T_ + t0 + 2)) * D_ + d] = c2;
    c_out[((long)(b * T_ + t0 + 3)) * D_ + d] = c3;
}

// ---------------------------------------------------------------------------
extern "C" void kernel_launch(void* const* d_in, const int* in_sizes, int n_in,
                              void* d_out, int out_size)
{
    const float* inp     = (const float*)d_in[0];
    const float* context = (const float*)d_in[1];
    const float* Wq      = (const float*)d_in[2];
    const float* bq      = (const float*)d_in[3];
    const float* Wc      = (const float*)d_in[4];
    const float* v       = (const float*)d_in[5];
    const float* Wout    = (const float*)d_in[6];
    const float* bout    = (const float*)d_in[7];

    float* out    = (float*)d_out;
    float* attn_h = out;                         // (B,T,D)
    float* align  = out + (long)B_ * T_ * D_;    // (B,T,S)

    float *p_wq, *p_uh, *p_pre, *p_c;
    cudaGetSymbolAddress((void**)&p_wq, g_wq);
    cudaGetSymbolAddress((void**)&p_uh, g_uh);
    cudaGetSymbolAddress((void**)&p_pre, g_pre);
    cudaGetSymbolAddress((void**)&p_c, g_c);

    // ---- Launch 1: fused {wq, uh, pre} GEMMs, all K=512, BM=64 ----
    GemmArgs a1;
    // seg0: wq = inp @ Wq^T + bq             (M=512 -> 8 blocks)
    a1.A[0] = inp;     a1.W[0] = Wq;          a1.bias[0] = bq;      a1.addC[0] = nullptr;
    a1.C[0] = p_wq;    a1.lda[0] = D_;        a1.ldw[0] = D_;       a1.ldc[0] = D_;
    // seg1: uh = context @ Wc^T              (M=2048 -> 32 blocks)
    a1.A[1] = context; a1.W[1] = Wc;          a1.bias[1] = nullptr; a1.addC[1] = nullptr;
    a1.C[1] = p_uh;    a1.lda[1] = D_;        a1.ldw[1] = D_;       a1.ldc[1] = D_;
    // seg2: pre = inp @ WoutR^T + bout       (M=512 -> 8 blocks)
    a1.A[2] = inp;     a1.W[2] = Wout + D_;   a1.bias[2] = bout;    a1.addC[2] = nullptr;
    a1.C[2] = p_pre;   a1.lda[2] = D_;        a1.ldw[2] = 2 * D_;   a1.ldc[2] = D_;
    a1.segEnd[0] = 8; a1.segEnd[1] = 40; a1.segEnd[2] = 48;
    gemm_seg_kernel<<<dim3(48, 8, 1), 256>>>(a1, D_);

    // ---- Launch 2: fused scores + softmax + context vectors ----
    attn_kernel<<<dim3(T_ / 4, B_), 512>>>(p_wq, p_uh, v, context, align, p_c);

    // ---- Launch 3: attn_h = c @ WoutL^T + pre  (full K, epilogue fold) ----
    GemmArgs a3;
    a3.A[0] = p_c;  a3.W[0] = Wout;  a3.bias[0] = nullptr;  a3.addC[0] = p_pre;
    a3.C[0] = attn_h;
    a3.lda[0] = D_; a3.ldw[0] = 2 * D_; a3.ldc[0] = D_;
    a3.A[1] = a3.A[0]; a3.W[1] = a3.W[0]; a3.bias[1] = nullptr; a3.addC[1] = nullptr;
    a3.C[1] = a3.C[0]; a3.lda[1] = a3.lda[0]; a3.ldw[1] = a3.ldw[0]; a3.ldc[1] = a3.ldc[0];
    a3.A[2] = a3.A[0]; a3.W[2] = a3.W[0]; a3.bias[2] = nullptr; a3.addC[2] = nullptr;
    a3.C[2] = a3.C[0]; a3.lda[2] = a3.lda[0]; a3.ldw[2] = a3.ldw[0]; a3.ldc[2] = a3.ldc[0];
    a3.segEnd[0] = 8; a3.segEnd[1] = 8; a3.segEnd[2] = 8;
    gemm_seg_kernel<<<dim3(8, 8, 1), 256>>>(a3, D_);
}